// round 16
// baseline (speedup 1.0000x reference)
#include <cuda_runtime.h>
#include <cuda_fp16.h>
#include <cstdint>

#define M_TOK   100352      // 32 * 56 * 56
#define DIM     256
#define QKV_N   768
#define HEADS   8
#define HD      32
#define WS      7
#define NT      49
#define SCALE   0.17677669529663687f

// Scratch (device globals: allocation-free per harness rules)
__device__ __half g_qkv[(size_t)M_TOK * QKV_N];   // 154 MB fp16
__device__ __half g_attn[(size_t)M_TOK * DIM];    // 51 MB fp16
__device__ __half g_x16[(size_t)M_TOK * DIM];     // 51 MB fp16 x
__device__ float  g_bias[NT * NT];
__device__ __half g_wqkvT[QKV_N * DIM];           // transposed fp16 (q-cols pre-scaled)
__device__ __half g_woutT[DIM * DIM];             // transposed fp16

__device__ __forceinline__ uint32_t smem_u32(const void* p) {
    uint32_t a;
    asm("{ .reg .u64 t; cvta.to.shared.u64 t, %1; cvt.u32.u64 %0, t; }"
        : "=r"(a) : "l"(p));
    return a;
}
__device__ __forceinline__ void cpasync16(uint32_t dst, const void* src) {
    asm volatile("cp.async.ca.shared.global [%0], [%1], 16;"
                 :: "r"(dst), "l"(src));
}
__device__ __forceinline__ void mma_f16(float* c, uint32_t a0, uint32_t a1,
                                        uint32_t a2, uint32_t a3,
                                        uint32_t b0, uint32_t b1) {
    asm volatile(
        "mma.sync.aligned.m16n8k16.row.col.f32.f16.f16.f32 "
        "{%0,%1,%2,%3}, {%4,%5,%6,%7}, {%8,%9}, {%0,%1,%2,%3};"
        : "+f"(c[0]), "+f"(c[1]), "+f"(c[2]), "+f"(c[3])
        : "r"(a0), "r"(a1), "r"(a2), "r"(a3), "r"(b0), "r"(b1));
}
__device__ __forceinline__ void ldsm_x4(uint32_t& r0, uint32_t& r1,
                                        uint32_t& r2, uint32_t& r3, uint32_t addr) {
    asm volatile("ldmatrix.sync.aligned.m8n8.x4.shared.b16 {%0,%1,%2,%3}, [%4];"
                 : "=r"(r0), "=r"(r1), "=r"(r2), "=r"(r3) : "r"(addr));
}
__device__ __forceinline__ uint32_t pack_h2(float lo, float hi) {
    __half2 h = __floats2half2_rn(lo, hi);
    return *(uint32_t*)&h;
}

// ---------------------------------------------------------------------------
// fp16 m16n8k16 GEMM, ldmatrix fragments, 3-stage cp.async pipeline.
// EXACT R12 structure (best known: 357us). Double barrier per chunk is
// load-bearing: stage written at iter c aliases stage read at iter c-1.
// ---------------------------------------------------------------------------
#define PH     40            // pitch in halves
#define PHB    80            // pitch bytes
#define ATILEB (128 * PHB)
#define STAGEB (2 * ATILEB)
#define NSTAGE 3

template<bool HALF_OUT>
__global__ __launch_bounds__(256, 2) void hgemm(
    const __half* __restrict__ A, const __half* __restrict__ BT,
    void* __restrict__ Cv, const float* __restrict__ bias, int N, int K)
{
    extern __shared__ __half smh[];
    const uint32_t smbase = smem_u32(smh);

    const int tid  = threadIdx.x;
    const int wid  = tid >> 5;
    const int lane = tid & 31;
    const int group = lane >> 2;
    const int tig   = lane & 3;
    const int m0w = (wid & 1) * 64;
    const int n0w = (wid >> 1) * 32;
    const int bm = blockIdx.y * 128;
    const int bn = blockIdx.x * 128;

    const int lrow = tid >> 2;
    const int lseg = tid & 3;

    float c[4][4][4];
#pragma unroll
    for (int mt = 0; mt < 4; mt++)
#pragma unroll
        for (int nt = 0; nt < 4; nt++)
#pragma unroll
            for (int r = 0; r < 4; r++) c[mt][nt][r] = 0.f;

    const int nch = K >> 5;

    auto issue = [&](int cc, int st) {
        const int k0 = cc * 32;
        const uint32_t sb = smbase + (uint32_t)st * STAGEB;
#pragma unroll
        for (int i = 0; i < 2; i++) {
            const int row = lrow + 64 * i;
            cpasync16(sb + (uint32_t)(row * PHB + lseg * 16),
                      &A[(size_t)(bm + row) * K + k0 + lseg * 8]);
            cpasync16(sb + (uint32_t)(ATILEB + row * PHB + lseg * 16),
                      &BT[(size_t)(bn + row) * K + k0 + lseg * 8]);
        }
    };

    issue(0, 0);
    asm volatile("cp.async.commit_group;");
    if (nch > 1) issue(1, 1);
    asm volatile("cp.async.commit_group;");

    const int arow = m0w + (lane & 15);
    const uint32_t acol = ((uint32_t)(lane >> 4)) * 16;
    const int browb = n0w + 8 * (lane >> 4) + (lane & 7);
    const uint32_t bcol = ((uint32_t)((lane >> 3) & 1)) * 16;

    for (int cidx = 0; cidx < nch; cidx++) {
        const int st = cidx % NSTAGE;
        asm volatile("cp.async.wait_group 1;");
        __syncthreads();

        const uint32_t sb = smbase + (uint32_t)st * STAGEB;
#pragma unroll
        for (int k16 = 0; k16 < 2; k16++) {
            const uint32_t koff = (uint32_t)k16 * 32;
            uint32_t a[4][4], b[4][2];
#pragma unroll
            for (int mt = 0; mt < 4; mt++) {
                uint32_t addr = sb + (uint32_t)((arow + mt * 16) * PHB) + acol + koff;
                ldsm_x4(a[mt][0], a[mt][1], a[mt][2], a[mt][3], addr);
            }
#pragma unroll
            for (int ntp = 0; ntp < 2; ntp++) {
                uint32_t addr = sb + ATILEB
                              + (uint32_t)((browb + 16 * ntp) * PHB) + bcol + koff;
                ldsm_x4(b[2 * ntp][0], b[2 * ntp][1],
                        b[2 * ntp + 1][0], b[2 * ntp + 1][1], addr);
            }
#pragma unroll
            for (int mt = 0; mt < 4; mt++)
#pragma unroll
                for (int nt = 0; nt < 4; nt++)
                    mma_f16(c[mt][nt], a[mt][0], a[mt][1], a[mt][2], a[mt][3],
                            b[nt][0], b[nt][1]);
        }
        __syncthreads();
        if (cidx + 2 < nch) {
            issue(cidx + 2, (cidx + 2) % NSTAGE);
        }
        asm volatile("cp.async.commit_group;");
    }

#pragma unroll
    for (int nt = 0; nt < 4; nt++) {
        const int col = bn + n0w + nt * 8 + tig * 2;
        float bv0 = 0.f, bv1 = 0.f;
        if (!HALF_OUT && bias) { bv0 = bias[col]; bv1 = bias[col + 1]; }
#pragma unroll
        for (int mt = 0; mt < 4; mt++) {
            const int row = bm + m0w + mt * 16 + group;
            if (HALF_OUT) {
                __half* Ch = (__half*)Cv;
                *(__half2*)&Ch[(size_t)row * N + col] =
                    __floats2half2_rn(c[mt][nt][0], c[mt][nt][1]);
                *(__half2*)&Ch[(size_t)(row + 8) * N + col] =
                    __floats2half2_rn(c[mt][nt][2], c[mt][nt][3]);
            } else {
                float* Cf = (float*)Cv;
                *(float2*)&Cf[(size_t)row * N + col] =
                    make_float2(c[mt][nt][0] + bv0, c[mt][nt][1] + bv1);
                *(float2*)&Cf[(size_t)(row + 8) * N + col] =
                    make_float2(c[mt][nt][2] + bv0, c[mt][nt][3] + bv1);
            }
        }
    }
}

// ---------------------------------------------------------------------------
__global__ void f2h_kernel(const float* __restrict__ in,
                           __half* __restrict__ out, int n4)
{
    int i = blockIdx.x * 256 + threadIdx.x;
    if (i < n4) {
        float4 v = ((const float4*)in)[i];
        ((__half2*)out)[2 * i]     = __floats2half2_rn(v.x, v.y);
        ((__half2*)out)[2 * i + 1] = __floats2half2_rn(v.z, v.w);
    }
}

// transpose + optional column scaling (n < scale_cut gets * SCALE)
__global__ void transpose_kernel(const float* __restrict__ W,
                                 __half* __restrict__ WT, int R, int Cc,
                                 int scale_cut)
{
    __shared__ float t[32][33];
    int x = blockIdx.x * 32 + threadIdx.x;
    int y = blockIdx.y * 32 + threadIdx.y;
    if (x < Cc && y < R) t[threadIdx.y][threadIdx.x] = W[y * Cc + x];
    __syncthreads();
    x = blockIdx.y * 32 + threadIdx.x;   // k
    y = blockIdx.x * 32 + threadIdx.y;   // n
    if (x < R && y < Cc) {
        float v = t[threadIdx.x][threadIdx.y];
        if (y < scale_cut) v *= SCALE;
        WT[y * R + x] = __float2half_rn(v);
    }
}

__global__ void bias_kernel(const float* __restrict__ pos_emb,
                            float* __restrict__ biasG)
{
    int e = blockIdx.x * 256 + threadIdx.x;
    if (e < NT * NT) {
        int i = e / NT, j = e - i * NT;
        int dx = j / WS - i / WS + (WS - 1);
        int dy = j % WS - i % WS + (WS - 1);
        biasG[e] = pos_emb[dx * (2 * WS - 1) + dy];
    }
}

// ---------------------------------------------------------------------------
// Window attention: fp16 mma + ldmatrix, TWO heads per block (grid (64,4,32),
// 256 threads). Heads 2h,2h+1 are adjacent 64B column slices of qkv -> the
// shared gather reads 128B contiguous per row per tensor. SCALE pre-folded
// into w_qkv's q-columns, so softmax is just sfrag + bias.
// ---------------------------------------------------------------------------
#define QP  40    // q/k pitch (halves)
#define QPB 80
#define VP  72    // vsT pitch (halves)
#define VPB 144

__global__ __launch_bounds__(256) void attn_kernel(
    const __half* __restrict__ qkv,
    const float* __restrict__ biasG,
    __half* __restrict__ out)
{
    __shared__ __half qs[2][64 * QP];    // rows 49..63 zero
    __shared__ __half ks[2][64 * QP];
    __shared__ __half vsT[2][32 * VP];   // [d][j], cols 49..63 zero
    __shared__ int    rowbase[NT];

    const int tid  = threadIdx.x;
    const int g    = tid >> 7;           // head sub-index within pair
    const int gtid = tid & 127;
    const int wm   = gtid >> 5;
    const int lane = tid & 31;
    const int group = lane >> 2;
    const int tig   = lane & 3;
    const int w  = blockIdx.x;
    const int hp = blockIdx.y;           // head pair
    const int b  = blockIdx.z;
    const int h  = hp * 2 + g;
    const int wr = w >> 3, wc = w & 7;

    if (tid < NT) {
        int ty = tid / WS, tx = tid - ty * WS;
        rowbase[tid] = (b * 56 + wr * WS + ty) * 56 + wc * WS + tx;
    }
    // zero pad rows (each group its own buffers)
    for (int i = gtid; i < 15 * 32; i += 128) {
        int r = 49 + i / 32, c = i & 31;
        qs[g][r * QP + c] = __float2half(0.f);
        ks[g][r * QP + c] = __float2half(0.f);
    }
    for (int i = gtid; i < 32 * VP / 2; i += 128)
        ((uint32_t*)vsT[g])[i] = 0u;
    __syncthreads();

    // Shared gather: both heads' slices are contiguous (128B per row per tensor)
    for (int f = tid; f < NT * 8; f += 256) {
        int t = f >> 3, seg = f & 7;
        int hh = seg >> 2, s4 = seg & 3;
        size_t base = (size_t)rowbase[t] * QKV_N + hp * 64 + seg * 8;
        uint4 qv = *(const uint4*)&qkv[base];
        uint4 kv = *(const uint4*)&qkv[base + 256];
        uint4 vv = *(const uint4*)&qkv[base + 512];
        *(uint4*)&qs[hh][t * QP + s4 * 8] = qv;
        *(uint4*)&ks[hh][t * QP + s4 * 8] = kv;
        const __half* vh = (const __half*)&vv;
#pragma unroll
        for (int d = 0; d < 8; d++)
            vsT[hh][(s4 * 8 + d) * VP + t] = vh[d];
    }
    __syncthreads();

    const uint32_t qsa = smem_u32(qs[g]);
    const uint32_t ksa = smem_u32(ks[g]);
    const uint32_t vta = smem_u32(vsT[g]);
    const int row_lo = 16 * wm + group;
    const int row_hi = row_lo + 8;

    float sfrag[8][4];
#pragma unroll
    for (int jt = 0; jt < 8; jt++)
#pragma unroll
        for (int r = 0; r < 4; r++) sfrag[jt][r] = 0.f;

    const uint32_t a_addr0 = qsa + (uint32_t)((16 * wm + (lane & 15)) * QPB)
                           + ((uint32_t)(lane >> 4)) * 16;
    const uint32_t b_row  = (uint32_t)(8 * (lane >> 4) + (lane & 7));
    const uint32_t b_coff = ((uint32_t)((lane >> 3) & 1)) * 16;

#pragma unroll
    for (int k16 = 0; k16 < 2; k16++) {
        const uint32_t koff = (uint32_t)k16 * 32;
        uint32_t a0, a1, a2, a3;
        ldsm_x4(a0, a1, a2, a3, a_addr0 + koff);
        uint32_t bqk[8][2];
#pragma unroll
        for (int p = 0; p < 4; p++) {
            uint32_t addr = ksa + (uint32_t)((16 * p + b_row) * QPB) + b_coff + koff;
            ldsm_x4(bqk[2 * p][0], bqk[2 * p][1],
                    bqk[2 * p + 1][0], bqk[2 * p + 1][1], addr);
        }
#pragma unroll
        for (int jt = 0; jt < 8; jt++)
            mma_f16(sfrag[jt], a0, a1, a2, a3, bqk[jt][0], bqk[jt][1]);
    }

    // softmax on fragments (SCALE already folded into q via weights)
    float m_lo = -1e30f, m_hi = -1e30f;
#pragma unroll
    for (int jt = 0; jt < 8; jt++) {
        const int col0 = 8 * jt + 2 * tig;
#pragma unroll
        for (int r = 0; r < 4; r++) {
            const int col = col0 + (r & 1);
            const int row = (r < 2) ? row_lo : row_hi;
            float val;
            if (row < NT && col < NT)
                val = sfrag[jt][r] + __ldg(&biasG[row * NT + col]);
            else
                val = -1e30f;
            sfrag[jt][r] = val;
            if (r < 2) m_lo = fmaxf(m_lo, val); else m_hi = fmaxf(m_hi, val);
        }
    }
    m_lo = fmaxf(m_lo, __shfl_xor_sync(0xffffffffu, m_lo, 1));
    m_lo = fmaxf(m_lo, __shfl_xor_sync(0xffffffffu, m_lo, 2));
    m_hi = fmaxf(m_hi, __shfl_xor_sync(0xffffffffu, m_hi, 1));
    m_hi = fmaxf(m_hi, __shfl_xor_sync(0xffffffffu, m_hi, 2));

    float s_lo = 0.f, s_hi = 0.f;
#pragma unroll
    for (int jt = 0; jt < 8; jt++) {
#pragma unroll
        for (int r = 0; r < 4; r++) {
            float e = __expf(sfrag[jt][r] - ((r < 2) ? m_lo : m_hi));
            sfrag[jt][r] = e;
            if (r < 2) s_lo += e; else s_hi += e;
        }
    }
    s_lo += __shfl_xor_sync(0xffffffffu, s_lo, 1);
    s_lo += __shfl_xor_sync(0xffffffffu, s_lo, 2);
    s_hi += __shfl_xor_sync(0xffffffffu, s_hi, 1);
    s_hi += __shfl_xor_sync(0xffffffffu, s_hi, 2);

    float o[4][4];
#pragma unroll
    for (int nt = 0; nt < 4; nt++)
#pragma unroll
        for (int r = 0; r < 4; r++) o[nt][r] = 0.f;

#pragma unroll
    for (int kt = 0; kt < 4; kt++) {
        const int jA = 2 * kt, jB = 2 * kt + 1;
        uint32_t a0 = pack_h2(sfrag[jA][0], sfrag[jA][1]);
        uint32_t a1 = pack_h2(sfrag[jA][2], sfrag[jA][3]);
        uint32_t a2 = pack_h2(sfrag[jB][0], sfrag[jB][1]);
        uint32_t a3 = pack_h2(sfrag[jB][2], sfrag[jB][3]);

        uint32_t bv[4][2];
#pragma unroll
        for (int dp = 0; dp < 2; dp++) {
            uint32_t addr = vta + (uint32_t)((16 * dp + b_row) * VPB)
                          + b_coff + (uint32_t)kt * 32;
            ldsm_x4(bv[2 * dp][0], bv[2 * dp][1],
                    bv[2 * dp + 1][0], bv[2 * dp + 1][1], addr);
        }
#pragma unroll
        for (int nt = 0; nt < 4; nt++)
            mma_f16(o[nt], a0, a1, a2, a3, bv[nt][0], bv[nt][1]);
    }

    const float inv_lo = 1.f / s_lo;
    const float inv_hi = 1.f / s_hi;
    if (row_lo < NT) {
        __half* orow = &out[(size_t)rowbase[row_lo] * DIM + h * HD];
#pragma unroll
        for (int nt = 0; nt < 4; nt++)
            *(__half2*)&orow[8 * nt + 2 * tig] =
                __floats2half2_rn(o[nt][0] * inv_lo, o[nt][1] * inv_lo);
    }
    if (row_hi < NT) {
        __half* orow = &out[(size_t)rowbase[row_hi] * DIM + h * HD];
#pragma unroll
        for (int nt = 0; nt < 4; nt++)
            *(__half2*)&orow[8 * nt + 2 * tig] =
                __floats2half2_rn(o[nt][2] * inv_hi, o[nt][3] * inv_hi);
    }
}

// ---------------------------------------------------------------------------
extern "C" void kernel_launch(void* const* d_in, const int* in_sizes, int n_in,
                              void* d_out, int out_size)
{
    const float* x      = (const float*)d_in[0];
    const float* w_qkv  = (const float*)d_in[1];
    const float* w_out  = (const float*)d_in[2];
    const float* b_out  = (const float*)d_in[3];
    const float* pos    = (const float*)d_in[4];
    float* out = (float*)d_out;

    __half *qkv_ptr, *attn_ptr, *x16_ptr, *wqkvT_ptr, *woutT_ptr;
    float *bias_ptr;
    cudaGetSymbolAddress((void**)&qkv_ptr,  g_qkv);
    cudaGetSymbolAddress((void**)&attn_ptr, g_attn);
    cudaGetSymbolAddress((void**)&x16_ptr,  g_x16);
    cudaGetSymbolAddress((void**)&bias_ptr, g_bias);
    cudaGetSymbolAddress((void**)&wqkvT_ptr, g_wqkvT);
    cudaGetSymbolAddress((void**)&woutT_ptr, g_woutT);

    const int SMEM_BYTES = NSTAGE * STAGEB;   // 61440
    static bool attr_set = false;
    if (!attr_set) {
        cudaFuncSetAttribute(hgemm<true>,
            cudaFuncAttributeMaxDynamicSharedMemorySize, SMEM_BYTES);
        cudaFuncSetAttribute(hgemm<false>,
            cudaFuncAttributeMaxDynamicSharedMemorySize, SMEM_BYTES);
        attr_set = true;
    }

    // 0) prep
    bias_kernel<<<(NT * NT + 255) / 256, 256>>>(pos, bias_ptr);
    {
        dim3 blk(32, 32);
        // q-columns (n < 256) pre-scaled by SCALE
        transpose_kernel<<<dim3(QKV_N / 32, DIM / 32), blk>>>(w_qkv, wqkvT_ptr, DIM, QKV_N, 256);
        transpose_kernel<<<dim3(DIM / 32, DIM / 32), blk>>>(w_out, woutT_ptr, DIM, DIM, 0);
    }
    {
        int n4 = M_TOK * DIM / 4;
        f2h_kernel<<<(n4 + 255) / 256, 256>>>(x, x16_ptr, n4);
    }

    // 1) qkv = x @ w_qkv   (fp16 mma, fp16 out; q pre-scaled)
    {
        dim3 grid(QKV_N / 128, M_TOK / 128);
        hgemm<true><<<grid, 256, SMEM_BYTES>>>(x16_ptr, wqkvT_ptr, qkv_ptr, nullptr, QKV_N, DIM);
    }
    // 2) window attention (2 heads per block)
    {
        dim3 grid(64, HEADS / 2, 32);
        attn_kernel<<<grid, 256>>>(qkv_ptr, bias_ptr, attn_ptr);
    }
    // 3) out = attn @ w_out + b_out   (fp16 mma, fp32 out + bias)
    {
        dim3 grid(DIM / 128, M_TOK / 128);
        hgemm<false><<<grid, 256, SMEM_BYTES>>>(attn_ptr, woutT_ptr, out, b_out, DIM, DIM);
    }
}

// round 17
// speedup vs baseline: 1.0187x; 1.0187x over previous
#include <cuda_runtime.h>
#include <cuda_fp16.h>
#include <cstdint>

#define M_TOK   100352      // 32 * 56 * 56
#define DIM     256
#define QKV_N   768
#define HEADS   8
#define HD      32
#define WS      7
#define NT      49
#define SCALE   0.17677669529663687f

// Scratch (device globals: allocation-free per harness rules)
__device__ __half g_qkv[(size_t)M_TOK * QKV_N];   // 154 MB fp16
__device__ __half g_attn[(size_t)M_TOK * DIM];    // 51 MB fp16
__device__ __half g_x16[(size_t)M_TOK * DIM];     // 51 MB fp16 x
__device__ float  g_bias[NT * NT];
__device__ __half g_wqkvT[QKV_N * DIM];           // transposed fp16 (q-cols pre-scaled)
__device__ __half g_woutT[DIM * DIM];             // transposed fp16

__device__ __forceinline__ uint32_t smem_u32(const void* p) {
    uint32_t a;
    asm("{ .reg .u64 t; cvta.to.shared.u64 t, %1; cvt.u32.u64 %0, t; }"
        : "=r"(a) : "l"(p));
    return a;
}
__device__ __forceinline__ void cpasync16(uint32_t dst, const void* src) {
    asm volatile("cp.async.ca.shared.global [%0], [%1], 16;"
                 :: "r"(dst), "l"(src));
}
__device__ __forceinline__ void mma_f16(float* c, uint32_t a0, uint32_t a1,
                                        uint32_t a2, uint32_t a3,
                                        uint32_t b0, uint32_t b1) {
    asm volatile(
        "mma.sync.aligned.m16n8k16.row.col.f32.f16.f16.f32 "
        "{%0,%1,%2,%3}, {%4,%5,%6,%7}, {%8,%9}, {%0,%1,%2,%3};"
        : "+f"(c[0]), "+f"(c[1]), "+f"(c[2]), "+f"(c[3])
        : "r"(a0), "r"(a1), "r"(a2), "r"(a3), "r"(b0), "r"(b1));
}
__device__ __forceinline__ void ldsm_x4(uint32_t& r0, uint32_t& r1,
                                        uint32_t& r2, uint32_t& r3, uint32_t addr) {
    asm volatile("ldmatrix.sync.aligned.m8n8.x4.shared.b16 {%0,%1,%2,%3}, [%4];"
                 : "=r"(r0), "=r"(r1), "=r"(r2), "=r"(r3) : "r"(addr));
}
__device__ __forceinline__ uint32_t pack_h2(float lo, float hi) {
    __half2 h = __floats2half2_rn(lo, hi);
    return *(uint32_t*)&h;
}

// ---------------------------------------------------------------------------
// fp16 m16n8k16 GEMM, ldmatrix fragments, 3-stage cp.async pipeline.
// EXACT R12 structure (best known: 357us). Double barrier per chunk is
// load-bearing: stage written at iter c aliases stage read at iter c-1.
// ---------------------------------------------------------------------------
#define PH     40            // pitch in halves
#define PHB    80            // pitch bytes
#define ATILEB (128 * PHB)
#define STAGEB (2 * ATILEB)
#define NSTAGE 3

template<bool HALF_OUT>
__global__ __launch_bounds__(256, 2) void hgemm(
    const __half* __restrict__ A, const __half* __restrict__ BT,
    void* __restrict__ Cv, const float* __restrict__ bias, int N, int K)
{
    extern __shared__ __half smh[];
    const uint32_t smbase = smem_u32(smh);

    const int tid  = threadIdx.x;
    const int wid  = tid >> 5;
    const int lane = tid & 31;
    const int group = lane >> 2;
    const int tig   = lane & 3;
    const int m0w = (wid & 1) * 64;
    const int n0w = (wid >> 1) * 32;
    const int bm = blockIdx.y * 128;
    const int bn = blockIdx.x * 128;

    const int lrow = tid >> 2;
    const int lseg = tid & 3;

    float c[4][4][4];
#pragma unroll
    for (int mt = 0; mt < 4; mt++)
#pragma unroll
        for (int nt = 0; nt < 4; nt++)
#pragma unroll
            for (int r = 0; r < 4; r++) c[mt][nt][r] = 0.f;

    const int nch = K >> 5;

    auto issue = [&](int cc, int st) {
        const int k0 = cc * 32;
        const uint32_t sb = smbase + (uint32_t)st * STAGEB;
#pragma unroll
        for (int i = 0; i < 2; i++) {
            const int row = lrow + 64 * i;
            cpasync16(sb + (uint32_t)(row * PHB + lseg * 16),
                      &A[(size_t)(bm + row) * K + k0 + lseg * 8]);
            cpasync16(sb + (uint32_t)(ATILEB + row * PHB + lseg * 16),
                      &BT[(size_t)(bn + row) * K + k0 + lseg * 8]);
        }
    };

    issue(0, 0);
    asm volatile("cp.async.commit_group;");
    if (nch > 1) issue(1, 1);
    asm volatile("cp.async.commit_group;");

    const int arow = m0w + (lane & 15);
    const uint32_t acol = ((uint32_t)(lane >> 4)) * 16;
    const int browb = n0w + 8 * (lane >> 4) + (lane & 7);
    const uint32_t bcol = ((uint32_t)((lane >> 3) & 1)) * 16;

    for (int cidx = 0; cidx < nch; cidx++) {
        const int st = cidx % NSTAGE;
        asm volatile("cp.async.wait_group 1;");
        __syncthreads();

        const uint32_t sb = smbase + (uint32_t)st * STAGEB;
#pragma unroll
        for (int k16 = 0; k16 < 2; k16++) {
            const uint32_t koff = (uint32_t)k16 * 32;
            uint32_t a[4][4], b[4][2];
#pragma unroll
            for (int mt = 0; mt < 4; mt++) {
                uint32_t addr = sb + (uint32_t)((arow + mt * 16) * PHB) + acol + koff;
                ldsm_x4(a[mt][0], a[mt][1], a[mt][2], a[mt][3], addr);
            }
#pragma unroll
            for (int ntp = 0; ntp < 2; ntp++) {
                uint32_t addr = sb + ATILEB
                              + (uint32_t)((browb + 16 * ntp) * PHB) + bcol + koff;
                ldsm_x4(b[2 * ntp][0], b[2 * ntp][1],
                        b[2 * ntp + 1][0], b[2 * ntp + 1][1], addr);
            }
#pragma unroll
            for (int mt = 0; mt < 4; mt++)
#pragma unroll
                for (int nt = 0; nt < 4; nt++)
                    mma_f16(c[mt][nt], a[mt][0], a[mt][1], a[mt][2], a[mt][3],
                            b[nt][0], b[nt][1]);
        }
        __syncthreads();
        if (cidx + 2 < nch) {
            issue(cidx + 2, (cidx + 2) % NSTAGE);
        }
        asm volatile("cp.async.commit_group;");
    }

#pragma unroll
    for (int nt = 0; nt < 4; nt++) {
        const int col = bn + n0w + nt * 8 + tig * 2;
        float bv0 = 0.f, bv1 = 0.f;
        if (!HALF_OUT && bias) { bv0 = bias[col]; bv1 = bias[col + 1]; }
#pragma unroll
        for (int mt = 0; mt < 4; mt++) {
            const int row = bm + m0w + mt * 16 + group;
            if (HALF_OUT) {
                __half* Ch = (__half*)Cv;
                *(__half2*)&Ch[(size_t)row * N + col] =
                    __floats2half2_rn(c[mt][nt][0], c[mt][nt][1]);
                *(__half2*)&Ch[(size_t)(row + 8) * N + col] =
                    __floats2half2_rn(c[mt][nt][2], c[mt][nt][3]);
            } else {
                float* Cf = (float*)Cv;
                *(float2*)&Cf[(size_t)row * N + col] =
                    make_float2(c[mt][nt][0] + bv0, c[mt][nt][1] + bv1);
                *(float2*)&Cf[(size_t)(row + 8) * N + col] =
                    make_float2(c[mt][nt][2] + bv0, c[mt][nt][3] + bv1);
            }
        }
    }
}

// ---------------------------------------------------------------------------
__global__ void f2h_kernel(const float* __restrict__ in,
                           __half* __restrict__ out, int n4)
{
    int i = blockIdx.x * 256 + threadIdx.x;
    if (i < n4) {
        float4 v = ((const float4*)in)[i];
        ((__half2*)out)[2 * i]     = __floats2half2_rn(v.x, v.y);
        ((__half2*)out)[2 * i + 1] = __floats2half2_rn(v.z, v.w);
    }
}

// transpose + optional column scaling (n < scale_cut gets * SCALE)
__global__ void transpose_kernel(const float* __restrict__ W,
                                 __half* __restrict__ WT, int R, int Cc,
                                 int scale_cut)
{
    __shared__ float t[32][33];
    int x = blockIdx.x * 32 + threadIdx.x;
    int y = blockIdx.y * 32 + threadIdx.y;
    if (x < Cc && y < R) t[threadIdx.y][threadIdx.x] = W[y * Cc + x];
    __syncthreads();
    x = blockIdx.y * 32 + threadIdx.x;   // k
    y = blockIdx.x * 32 + threadIdx.y;   // n
    if (x < R && y < Cc) {
        float v = t[threadIdx.x][threadIdx.y];
        if (y < scale_cut) v *= SCALE;
        WT[y * R + x] = __float2half_rn(v);
    }
}

__global__ void bias_kernel(const float* __restrict__ pos_emb,
                            float* __restrict__ biasG)
{
    int e = blockIdx.x * 256 + threadIdx.x;
    if (e < NT * NT) {
        int i = e / NT, j = e - i * NT;
        int dx = j / WS - i / WS + (WS - 1);
        int dy = j % WS - i % WS + (WS - 1);
        biasG[e] = pos_emb[dx * (2 * WS - 1) + dy];
    }
}

// ---------------------------------------------------------------------------
// Window attention: full fp16 mma + ldmatrix (EXACT R12: one head per block,
// 128 threads, __ldg bias). SCALE pre-folded into w_qkv's q-columns, so the
// softmax pass is add-bias only.
// ---------------------------------------------------------------------------
#define QP  40    // q/k pitch (halves)
#define QPB 80
#define VP  72    // vsT pitch (halves)
#define VPB 144

__global__ __launch_bounds__(128) void attn_kernel(
    const __half* __restrict__ qkv,
    const float* __restrict__ biasG,
    __half* __restrict__ out)
{
    __shared__ __half qs[64 * QP];    // rows 49..63 zero
    __shared__ __half ks[64 * QP];    // rows 49..63 zero
    __shared__ __half vsT[32 * VP];   // [d][j], cols 49..63 zero
    __shared__ int    rowbase[NT];

    const int tid = threadIdx.x;
    const int wm  = tid >> 5;
    const int lane = tid & 31;
    const int group = lane >> 2;
    const int tig   = lane & 3;
    const int w = blockIdx.x;
    const int h = blockIdx.y;
    const int b = blockIdx.z;
    const int wr = w >> 3, wc = w & 7;

    if (tid < NT) {
        int ty = tid / WS, tx = tid - ty * WS;
        rowbase[tid] = (b * 56 + wr * WS + ty) * 56 + wc * WS + tx;
    }
    for (int i = tid; i < 15 * 32; i += 128) {
        int r = 49 + i / 32, c = i & 31;
        qs[r * QP + c] = __float2half(0.f);
        ks[r * QP + c] = __float2half(0.f);
    }
    for (int i = tid; i < 32 * VP / 2; i += 128)
        ((uint32_t*)vsT)[i] = 0u;
    __syncthreads();

    for (int f = tid; f < NT * 4; f += 128) {
        int t = f >> 2, seg = f & 3;
        size_t base = (size_t)rowbase[t] * QKV_N + h * HD + seg * 8;
        uint4 qv = *(const uint4*)&qkv[base];
        uint4 kv = *(const uint4*)&qkv[base + 256];
        uint4 vv = *(const uint4*)&qkv[base + 512];
        *(uint4*)&qs[t * QP + seg * 8] = qv;
        *(uint4*)&ks[t * QP + seg * 8] = kv;
        const __half* vh = (const __half*)&vv;
#pragma unroll
        for (int d = 0; d < 8; d++)
            vsT[(seg * 8 + d) * VP + t] = vh[d];
    }
    __syncthreads();

    const uint32_t qsa = smem_u32(qs);
    const uint32_t ksa = smem_u32(ks);
    const uint32_t vta = smem_u32(vsT);
    const int row_lo = 16 * wm + group;
    const int row_hi = row_lo + 8;

    float sfrag[8][4];
#pragma unroll
    for (int jt = 0; jt < 8; jt++)
#pragma unroll
        for (int r = 0; r < 4; r++) sfrag[jt][r] = 0.f;

    const uint32_t a_addr0 = qsa + (uint32_t)((16 * wm + (lane & 15)) * QPB)
                           + ((uint32_t)(lane >> 4)) * 16;
    const uint32_t b_row  = (uint32_t)(8 * (lane >> 4) + (lane & 7));
    const uint32_t b_coff = ((uint32_t)((lane >> 3) & 1)) * 16;

#pragma unroll
    for (int k16 = 0; k16 < 2; k16++) {
        const uint32_t koff = (uint32_t)k16 * 32;
        uint32_t a0, a1, a2, a3;
        ldsm_x4(a0, a1, a2, a3, a_addr0 + koff);
        uint32_t bqk[8][2];
#pragma unroll
        for (int p = 0; p < 4; p++) {
            uint32_t addr = ksa + (uint32_t)((16 * p + b_row) * QPB) + b_coff + koff;
            ldsm_x4(bqk[2 * p][0], bqk[2 * p][1],
                    bqk[2 * p + 1][0], bqk[2 * p + 1][1], addr);
        }
#pragma unroll
        for (int jt = 0; jt < 8; jt++)
            mma_f16(sfrag[jt], a0, a1, a2, a3, bqk[jt][0], bqk[jt][1]);
    }

    // softmax on fragments (SCALE folded into q via weights)
    float m_lo = -1e30f, m_hi = -1e30f;
#pragma unroll
    for (int jt = 0; jt < 8; jt++) {
        const int col0 = 8 * jt + 2 * tig;
#pragma unroll
        for (int r = 0; r < 4; r++) {
            const int col = col0 + (r & 1);
            const int row = (r < 2) ? row_lo : row_hi;
            float val;
            if (row < NT && col < NT)
                val = sfrag[jt][r] + __ldg(&biasG[row * NT + col]);
            else
                val = -1e30f;
            sfrag[jt][r] = val;
            if (r < 2) m_lo = fmaxf(m_lo, val); else m_hi = fmaxf(m_hi, val);
        }
    }
    m_lo = fmaxf(m_lo, __shfl_xor_sync(0xffffffffu, m_lo, 1));
    m_lo = fmaxf(m_lo, __shfl_xor_sync(0xffffffffu, m_lo, 2));
    m_hi = fmaxf(m_hi, __shfl_xor_sync(0xffffffffu, m_hi, 1));
    m_hi = fmaxf(m_hi, __shfl_xor_sync(0xffffffffu, m_hi, 2));

    float s_lo = 0.f, s_hi = 0.f;
#pragma unroll
    for (int jt = 0; jt < 8; jt++) {
#pragma unroll
        for (int r = 0; r < 4; r++) {
            float e = __expf(sfrag[jt][r] - ((r < 2) ? m_lo : m_hi));
            sfrag[jt][r] = e;
            if (r < 2) s_lo += e; else s_hi += e;
        }
    }
    s_lo += __shfl_xor_sync(0xffffffffu, s_lo, 1);
    s_lo += __shfl_xor_sync(0xffffffffu, s_lo, 2);
    s_hi += __shfl_xor_sync(0xffffffffu, s_hi, 1);
    s_hi += __shfl_xor_sync(0xffffffffu, s_hi, 2);

    float o[4][4];
#pragma unroll
    for (int nt = 0; nt < 4; nt++)
#pragma unroll
        for (int r = 0; r < 4; r++) o[nt][r] = 0.f;

#pragma unroll
    for (int kt = 0; kt < 4; kt++) {
        const int jA = 2 * kt, jB = 2 * kt + 1;
        uint32_t a0 = pack_h2(sfrag[jA][0], sfrag[jA][1]);
        uint32_t a1 = pack_h2(sfrag[jA][2], sfrag[jA][3]);
        uint32_t a2 = pack_h2(sfrag[jB][0], sfrag[jB][1]);
        uint32_t a3 = pack_h2(sfrag[jB][2], sfrag[jB][3]);

        uint32_t bv[4][2];
#pragma unroll
        for (int dp = 0; dp < 2; dp++) {
            uint32_t addr = vta + (uint32_t)((16 * dp + b_row) * VPB)
                          + b_coff + (uint32_t)kt * 32;
            ldsm_x4(bv[2 * dp][0], bv[2 * dp][1],
                    bv[2 * dp + 1][0], bv[2 * dp + 1][1], addr);
        }
#pragma unroll
        for (int nt = 0; nt < 4; nt++)
            mma_f16(o[nt], a0, a1, a2, a3, bv[nt][0], bv[nt][1]);
    }

    const float inv_lo = 1.f / s_lo;
    const float inv_hi = 1.f / s_hi;
    if (row_lo < NT) {
        __half* orow = &out[(size_t)rowbase[row_lo] * DIM + h * HD];
#pragma unroll
        for (int nt = 0; nt < 4; nt++)
            *(__half2*)&orow[8 * nt + 2 * tig] =
                __floats2half2_rn(o[nt][0] * inv_lo, o[nt][1] * inv_lo);
    }
    if (row_hi < NT) {
        __half* orow = &out[(size_t)rowbase[row_hi] * DIM + h * HD];
#pragma unroll
        for (int nt = 0; nt < 4; nt++)
            *(__half2*)&orow[8 * nt + 2 * tig] =
                __floats2half2_rn(o[nt][2] * inv_hi, o[nt][3] * inv_hi);
    }
}

// ---------------------------------------------------------------------------
extern "C" void kernel_launch(void* const* d_in, const int* in_sizes, int n_in,
                              void* d_out, int out_size)
{
    const float* x      = (const float*)d_in[0];
    const float* w_qkv  = (const float*)d_in[1];
    const float* w_out  = (const float*)d_in[2];
    const float* b_out  = (const float*)d_in[3];
    const float* pos    = (const float*)d_in[4];
    float* out = (float*)d_out;

    __half *qkv_ptr, *attn_ptr, *x16_ptr, *wqkvT_ptr, *woutT_ptr;
    float *bias_ptr;
    cudaGetSymbolAddress((void**)&qkv_ptr,  g_qkv);
    cudaGetSymbolAddress((void**)&attn_ptr, g_attn);
    cudaGetSymbolAddress((void**)&x16_ptr,  g_x16);
    cudaGetSymbolAddress((void**)&bias_ptr, g_bias);
    cudaGetSymbolAddress((void**)&wqkvT_ptr, g_wqkvT);
    cudaGetSymbolAddress((void**)&woutT_ptr, g_woutT);

    const int SMEM_BYTES = NSTAGE * STAGEB;   // 61440
    static bool attr_set = false;
    if (!attr_set) {
        cudaFuncSetAttribute(hgemm<true>,
            cudaFuncAttributeMaxDynamicSharedMemorySize, SMEM_BYTES);
        cudaFuncSetAttribute(hgemm<false>,
            cudaFuncAttributeMaxDynamicSharedMemorySize, SMEM_BYTES);
        attr_set = true;
    }

    // 0) prep
    bias_kernel<<<(NT * NT + 255) / 256, 256>>>(pos, bias_ptr);
    {
        dim3 blk(32, 32);
        // q-columns (n < 256) pre-scaled by SCALE
        transpose_kernel<<<dim3(QKV_N / 32, DIM / 32), blk>>>(w_qkv, wqkvT_ptr, DIM, QKV_N, 256);
        transpose_kernel<<<dim3(DIM / 32, DIM / 32), blk>>>(w_out, woutT_ptr, DIM, DIM, 0);
    }
    {
        int n4 = M_TOK * DIM / 4;
        f2h_kernel<<<(n4 + 255) / 256, 256>>>(x, x16_ptr, n4);
    }

    // 1) qkv = x @ w_qkv   (fp16 mma, fp16 out; q pre-scaled)
    {
        dim3 grid(QKV_N / 128, M_TOK / 128);
        hgemm<true><<<grid, 256, SMEM_BYTES>>>(x16_ptr, wqkvT_ptr, qkv_ptr, nullptr, QKV_N, DIM);
    }
    // 2) window attention (one head per block — R12 best-known config)
    {
        dim3 grid(64, HEADS, 32);
        attn_kernel<<<grid, 128>>>(qkv_ptr, bias_ptr, attn_ptr);
    }
    // 3) out = attn @ w_out + b_out   (fp16 mma, fp32 out + bias)
    {
        dim3 grid(DIM / 128, M_TOK / 128);
        hgemm<false><<<grid, 256, SMEM_BYTES>>>(attn_ptr, woutT_ptr, out, b_out, DIM, DIM);
    }
}